// round 16
// baseline (speedup 1.0000x reference)
#include <cuda_runtime.h>
#include <cuda_bf16.h>
#include <math.h>
#include <stdint.h>

// Problem constants (fixed shapes from reference)
#define BB 4
#define LL 2048
#define DD 768
#define SS 16
#define MM (BB * LL)          // 8192
#define TWO_D (2 * DD)        // 1536
#define NC 16                 // scan chunks
#define LC (LL / NC)          // 128

// ---------------- scratch (device globals; no allocs allowed) ----------------
__device__ float g_xz[MM * TWO_D];     // in_proj output (x_gate | z)
__device__ float g_xconv[MM * DD];     // conv + silu output (f32, for bc/scan)
__device__ float g_dt[MM * DD];        // softplus(dt)
__device__ float g_bc[MM * 2 * SS];    // B | C
__device__ float g_P[BB * DD * NC * SS];
__device__ float g_hend[BB * DD * NC * SS];
__device__ float g_hin[BB * DD * NC * SS];

// bf16 hi/lo split operands (A operands [M][768] k-major; W^T [N][768] k-major)
__device__ __align__(16) uint16_t g_xhi[MM * DD],  g_xlo[MM * DD];
__device__ __align__(16) uint16_t g_xchi[MM * DD], g_xclo[MM * DD];
__device__ __align__(16) uint16_t g_yghi[MM * DD], g_yglo[MM * DD];
__device__ __align__(16) uint16_t g_wthi_in[TWO_D * DD],  g_wtlo_in[TWO_D * DD];
__device__ __align__(16) uint16_t g_wthi_dt[DD * DD],     g_wtlo_dt[DD * DD];
__device__ __align__(16) uint16_t g_wthi_out[DD * DD],    g_wtlo_out[DD * DD];

// ---------------- helpers ----------------
__device__ __forceinline__ void split2(float x0, float x1, uint32_t& hi, uint32_t& lo)
{
    uint32_t h;
    asm("cvt.rn.bf16x2.f32 %0, %1, %2;" : "=r"(h) : "f"(x1), "f"(x0));
    float h0 = __uint_as_float(h << 16);
    float h1 = __uint_as_float(h & 0xffff0000u);
    float l0 = x0 - h0;
    float l1 = x1 - h1;
    asm("cvt.rn.bf16x2.f32 %0, %1, %2;" : "=r"(lo) : "f"(l1), "f"(l0));
    hi = h;
}

__device__ __forceinline__ void split1(float v, uint16_t& h16, uint16_t& l16)
{
    __nv_bfloat16 hb = __float2bfloat16(v);
    float hf = __bfloat162float(hb);
    __nv_bfloat16 lb = __float2bfloat16(v - hf);
    h16 = *reinterpret_cast<uint16_t*>(&hb);
    l16 = *reinterpret_cast<uint16_t*>(&lb);
}

__device__ __forceinline__ void ldsm_x4(uint32_t& r0, uint32_t& r1,
                                        uint32_t& r2, uint32_t& r3, uint32_t addr)
{
    asm volatile("ldmatrix.sync.aligned.m8n8.x4.shared.b16 {%0,%1,%2,%3}, [%4];"
                 : "=r"(r0), "=r"(r1), "=r"(r2), "=r"(r3) : "r"(addr));
}

__device__ __forceinline__ void mma16816(float* c, const uint32_t* a, const uint32_t* b)
{
    asm volatile(
        "mma.sync.aligned.m16n8k16.row.col.f32.bf16.bf16.f32 "
        "{%0,%1,%2,%3}, {%4,%5,%6,%7}, {%8,%9}, {%0,%1,%2,%3};"
        : "+f"(c[0]), "+f"(c[1]), "+f"(c[2]), "+f"(c[3])
        : "r"(a[0]), "r"(a[1]), "r"(a[2]), "r"(a[3]), "r"(b[0]), "r"(b[1]));
}

__device__ __forceinline__ void cpa16(uint32_t dst, const void* src)
{
    asm volatile("cp.async.cg.shared.global [%0], [%1], 16;"
                 :: "r"(dst), "l"(src) : "memory");
}
#define CPA_COMMIT() asm volatile("cp.async.commit_group;" ::: "memory")

__device__ __forceinline__ uint32_t sw128(uint32_t off) { return off ^ ((off >> 3) & 0x70u); }

// ---------------- bf16 split GEMM on tensor cores (cp.async mainloop) --------
// C[M,N] = A[M,K] @ W[K,N], A as hi/lo bf16 [M][768] k-major, W^T as hi/lo
// bf16 [N][768] k-major. 3-product split (AhBh + AhBl + AlBh), fp32 acc.
// CTA tile 128(M) x 64(N), KT=32, double-buffered cp.async.
// smem row (128B, SW128): [hi 32k | lo 32k]. A 16KB + B 8KB, x2 bufs = 48KB.
// EPI: 0 = plain store, 1 = softplus(acc + bias[n])
template <int EPI>
__device__ __forceinline__ void bf_gemm_body(
    const uint16_t* __restrict__ Ahi, const uint16_t* __restrict__ Alo,
    const uint16_t* __restrict__ Bhi, const uint16_t* __restrict__ Blo,
    float* __restrict__ C, const float* __restrict__ bias, int N)
{
    __shared__ __align__(1024) uint8_t sm[2][24576];   // [buf][A 16KB | B 8KB]

    const int tid  = threadIdx.x;
    const int lane = tid & 31;
    const int wid  = tid >> 5;
    const int m_off = (wid >> 2) * 64;     // 2 warps in M
    const int n_off = (wid & 3) * 16;      // 4 warps in N (16 n each)
    const int m0 = blockIdx.y * 128;
    const int n0 = blockIdx.x * 64;

    const uint32_t smBase = (uint32_t)__cvta_generic_to_shared(&sm[0][0]);

    float acc[4][2][4];
#pragma unroll
    for (int i = 0; i < 4; i++)
#pragma unroll
        for (int j = 0; j < 2; j++)
#pragma unroll
            for (int r = 0; r < 4; r++) acc[i][j][r] = 0.f;

    const uint32_t aOffB = (uint32_t)((m_off + (lane & 15)) * 128 + 16 * (lane >> 4));
    const uint32_t bOffB = (uint32_t)((n_off + (lane & 15)) * 128 + 16 * (lane >> 4));

    auto cp_tile = [&](int p, int t) {
        uint32_t aBase = smBase + (uint32_t)(p * 24576);
        uint32_t bBase = aBase + 16384;
        // A: 128 rows x 8 chunks (0-3 hi, 4-7 lo) = 1024 chunks, 4/thread
#pragma unroll
        for (int i = 0; i < 4; i++) {
            int ch = tid + i * 256;
            int row = ch >> 3, slot = ch & 7;
            uint32_t dst = aBase + sw128((uint32_t)(row * 128 + slot * 16));
            const uint16_t* base = (slot < 4) ? Ahi : Alo;
            cpa16(dst, base + (size_t)(m0 + row) * DD + t * 32 + (slot & 3) * 8);
        }
        // B: 64 rows x 8 chunks = 512 chunks, 2/thread
#pragma unroll
        for (int i = 0; i < 2; i++) {
            int ch = tid + i * 256;
            int row = ch >> 3, slot = ch & 7;
            uint32_t dst = bBase + sw128((uint32_t)(row * 128 + slot * 16));
            const uint16_t* base = (slot < 4) ? Bhi : Blo;
            cpa16(dst, base + (size_t)(n0 + row) * DD + t * 32 + (slot & 3) * 8);
        }
        CPA_COMMIT();
    };

    cp_tile(0, 0);

    for (int t = 0; t < DD / 32; t++) {
        const bool more = (t + 1) < DD / 32;
        if (more) cp_tile((t + 1) & 1, t + 1);
        if (more) asm volatile("cp.async.wait_group 1;" ::: "memory");
        else      asm volatile("cp.async.wait_group 0;" ::: "memory");
        __syncthreads();

        const uint32_t aBase = smBase + (uint32_t)((t & 1) * 24576);
        const uint32_t bBase = aBase + 16384;

        uint32_t ah[4][4], al[4][4], bh[2][2], bl[2][2];
#pragma unroll
        for (int ks = 0; ks < 2; ks++) {
#pragma unroll
            for (int i = 0; i < 4; i++) {
                uint32_t off = aOffB + (uint32_t)(i * 2048 + ks * 32);
                ldsm_x4(ah[i][0], ah[i][1], ah[i][2], ah[i][3], aBase + sw128(off));
                ldsm_x4(al[i][0], al[i][1], al[i][2], al[i][3], aBase + sw128(off + 64));
            }
            {
                uint32_t off = bOffB + (uint32_t)(ks * 32);
                uint32_t r0, r1, r2, r3;
                ldsm_x4(r0, r1, r2, r3, bBase + sw128(off));
                bh[0][0] = r0; bh[0][1] = r2; bh[1][0] = r1; bh[1][1] = r3;
                ldsm_x4(r0, r1, r2, r3, bBase + sw128(off + 64));
                bl[0][0] = r0; bl[0][1] = r2; bl[1][0] = r1; bl[1][1] = r3;
            }
            if (ks == 1) __syncthreads();   // all reads done -> next cp_tile may overwrite
#pragma unroll
            for (int i = 0; i < 4; i++)
#pragma unroll
                for (int j = 0; j < 2; j++) {
                    mma16816(acc[i][j], ah[i], bh[j]);
                    mma16816(acc[i][j], ah[i], bl[j]);
                    mma16816(acc[i][j], al[i], bh[j]);
                }
        }
    }

    // epilogue
#pragma unroll
    for (int i = 0; i < 4; i++) {
        int row0 = m0 + m_off + 16 * i + (lane >> 2);
#pragma unroll
        for (int j = 0; j < 2; j++) {
            int col0 = n0 + n_off + 8 * j + 2 * (lane & 3);
            float v0 = acc[i][j][0], v1 = acc[i][j][1];
            float v2 = acc[i][j][2], v3 = acc[i][j][3];
            if (EPI == 1) {
                float b0 = bias[col0], b1 = bias[col0 + 1], tt;
                tt = v0 + b0; v0 = (tt > 20.f) ? tt : log1pf(expf(tt));
                tt = v1 + b1; v1 = (tt > 20.f) ? tt : log1pf(expf(tt));
                tt = v2 + b0; v2 = (tt > 20.f) ? tt : log1pf(expf(tt));
                tt = v3 + b1; v3 = (tt > 20.f) ? tt : log1pf(expf(tt));
            }
            *(float2*)&C[(size_t)row0 * N + col0] = make_float2(v0, v1);
            *(float2*)&C[(size_t)(row0 + 8) * N + col0] = make_float2(v2, v3);
        }
    }
}

// GEMM wrappers binding device globals (no device symbols cross the host ABI)
__global__ __launch_bounds__(256, 2) void bf_gemm_in_kernel()
{
    bf_gemm_body<0>(g_xhi, g_xlo, g_wthi_in, g_wtlo_in, g_xz, nullptr, TWO_D);
}
__global__ __launch_bounds__(256, 2) void bf_gemm_dt_kernel(const float* __restrict__ b_dt)
{
    bf_gemm_body<1>(g_xchi, g_xclo, g_wthi_dt, g_wtlo_dt, g_dt, b_dt, DD);
}
__global__ __launch_bounds__(256, 2) void bf_gemm_out_kernel(float* __restrict__ out)
{
    bf_gemm_body<0>(g_yghi, g_yglo, g_wthi_out, g_wtlo_out, out, nullptr, DD);
}

// ---------------- precompute: x -> bf16 hi/lo ----------------
__global__ void convert_x_kernel(const float* __restrict__ x)
{
    int i = blockIdx.x * 256 + threadIdx.x;     // float4 index
    if (i >= MM * DD / 4) return;
    float4 v = ((const float4*)x)[i];
    uint32_t h0, l0, h1, l1;
    split2(v.x, v.y, h0, l0);
    split2(v.z, v.w, h1, l1);
    ((uint2*)g_xhi)[i] = make_uint2(h0, h1);
    ((uint2*)g_xlo)[i] = make_uint2(l0, l1);
}

// ---------------- precompute: W [K][N] -> W^T hi/lo bf16 [N][K] ----------------
__device__ __forceinline__ void wtrans_body(
    const float* __restrict__ w, uint16_t* __restrict__ hi,
    uint16_t* __restrict__ lo, int N)
{
    __shared__ float tile[32][33];
    int n0 = blockIdx.x * 32, k0 = blockIdx.y * 32;
    int xi = threadIdx.x & 31, yi = threadIdx.x >> 5;   // 32 x 8
#pragma unroll
    for (int i = 0; i < 32; i += 8)
        tile[yi + i][xi] = w[(size_t)(k0 + yi + i) * N + n0 + xi];
    __syncthreads();
#pragma unroll
    for (int i = 0; i < 32; i += 8) {
        float v = tile[xi][yi + i];               // w[k0+xi][n0+yi+i]
        uint16_t h16, l16;
        split1(v, h16, l16);
        size_t o = (size_t)(n0 + yi + i) * DD + k0 + xi;
        hi[o] = h16;
        lo[o] = l16;
    }
}

__global__ __launch_bounds__(256) void wtrans_in_kernel(const float* __restrict__ w)
{
    wtrans_body(w, g_wthi_in, g_wtlo_in, TWO_D);
}
__global__ __launch_bounds__(256) void wtrans_dt_kernel(const float* __restrict__ w)
{
    wtrans_body(w, g_wthi_dt, g_wtlo_dt, DD);
}
__global__ __launch_bounds__(256) void wtrans_out_kernel(const float* __restrict__ w)
{
    wtrans_body(w, g_wthi_out, g_wtlo_out, DD);
}

// ---------------- causal depthwise conv (K=4) + bias + SiLU + bf16 split -----
__global__ void conv_silu_kernel(const float* __restrict__ cw,
                                 const float* __restrict__ cb)
{
    int idx = blockIdx.x * blockDim.x + threadIdx.x;
    if (idx >= MM * DD) return;
    int d  = idx % DD;
    int ml = idx / DD;
    int l  = ml % LL;

    float w0 = cw[d * 4 + 0], w1 = cw[d * 4 + 1];
    float w2 = cw[d * 4 + 2], w3 = cw[d * 4 + 3];
    const float* base = g_xz + (size_t)ml * TWO_D + d;

    float acc = cb[d];
    if (l >= 3) acc = fmaf(w0, base[-3 * TWO_D], acc);
    if (l >= 2) acc = fmaf(w1, base[-2 * TWO_D], acc);
    if (l >= 1) acc = fmaf(w2, base[-1 * TWO_D], acc);
    acc = fmaf(w3, base[0], acc);

    float sig = 1.f / (1.f + expf(-acc));
    float v = acc * sig;
    g_xconv[idx] = v;
    uint16_t h16, l16;
    split1(v, h16, l16);
    g_xchi[idx] = h16;
    g_xclo[idx] = l16;
}

// ---------------- BC = xconv @ w_x   (M=8192, N=32, K=768) ----------------
__global__ __launch_bounds__(256) void bc_gemm_kernel(const float* __restrict__ wx)
{
    __shared__ float ws[64][32];
    __shared__ float xs[128][65];

    const int tid  = threadIdx.x;
    const int row  = tid & 127;
    const int half = tid >> 7;
    const int row0 = blockIdx.x * 128;

    float acc[32];
#pragma unroll
    for (int n = 0; n < 32; n++) acc[n] = 0.f;

    for (int k0 = 0; k0 < DD; k0 += 64) {
#pragma unroll
        for (int i = 0; i < 2; i++) {
            int idx = tid + i * 256;
            int r = idx >> 3;
            int c4 = (idx & 7) * 4;
            *(float4*)&ws[r][c4] = *(const float4*)&wx[(size_t)(k0 + r) * 32 + c4];
        }
#pragma unroll
        for (int i = 0; i < 8; i++) {
            int idx = tid + i * 256;
            int r = idx >> 4;
            int c4 = (idx & 15) * 4;
            float4 v = *(const float4*)&g_xconv[(size_t)(row0 + r) * DD + k0 + c4];
            xs[r][c4 + 0] = v.x;
            xs[r][c4 + 1] = v.y;
            xs[r][c4 + 2] = v.z;
            xs[r][c4 + 3] = v.w;
        }
        __syncthreads();
#pragma unroll 4
        for (int k = 0; k < 32; k++) {
            int kk = half * 32 + k;
            float xv = xs[row][kk];
#pragma unroll
            for (int n = 0; n < 32; n++)
                acc[n] = fmaf(xv, ws[kk][n], acc[n]);
        }
        __syncthreads();
    }

    float* red = &xs[0][0];
    if (half == 1) {
#pragma unroll
        for (int n = 0; n < 32; n++) red[row * 33 + n] = acc[n];
    }
    __syncthreads();
    if (half == 0) {
#pragma unroll
        for (int n = 0; n < 32; n++) acc[n] += red[row * 33 + n];
        float* op = g_bc + (size_t)(row0 + row) * 32;
#pragma unroll
        for (int n4 = 0; n4 < 8; n4++) {
            float4 v;
            v.x = acc[n4 * 4 + 0];
            v.y = acc[n4 * 4 + 1];
            v.z = acc[n4 * 4 + 2];
            v.w = acc[n4 * 4 + 3];
            *(float4*)(op + n4 * 4) = v;
        }
    }
}

// ---------------- chunked selective scan (3 phases) ----------------
__global__ __launch_bounds__(256) void scan_phase1(const float* __restrict__ A_log)
{
    const int tid = threadIdx.x;
    const int s = tid & 15;
    const int G = blockIdx.x * 16 + (tid >> 4);
    const int d = G % DD;
    const int t2 = G / DD;
    const int c = t2 % NC;
    const int b = t2 / NC;

    const float Acoef = -expf(A_log[d * SS + s]);
    const int l0 = c * LC;
    const float* dtp = g_dt    + ((size_t)(b * LL + l0)) * DD + d;
    const float* xcp = g_xconv + ((size_t)(b * LL + l0)) * DD + d;
    const float* bcp = g_bc    + ((size_t)(b * LL + l0)) * 32;

    float h = 0.f, P = 1.f;
    for (int i = 0; i < LC; i++) {
        float dtv = dtp[(size_t)i * DD];
        float xcv = xcp[(size_t)i * DD];
        float Bv  = bcp[i * 32 + s];
        float dA = expf(dtv * Acoef);
        P *= dA;
        h = fmaf(dA, h, dtv * Bv * xcv);
    }
    int idx = (((b * DD + d) * NC) + c) * SS + s;
    g_P[idx] = P;
    g_hend[idx] = h;
}

__global__ __launch_bounds__(256) void scan_phase2()
{
    int t = blockIdx.x * 256 + threadIdx.x;
    int s = t & 15;
    int rest = t >> 4;
    int base = rest * NC * SS + s;
    float h = 0.f;
#pragma unroll
    for (int c = 0; c < NC; c++) {
        int idx = base + c * SS;
        g_hin[idx] = h;
        h = fmaf(g_P[idx], h, g_hend[idx]);
    }
}

__global__ __launch_bounds__(256) void scan_phase3(
    const float* __restrict__ A_log, const float* __restrict__ Dp)
{
    const int tid = threadIdx.x;
    const int s = tid & 15;
    const int G = blockIdx.x * 16 + (tid >> 4);
    const int d = G % DD;
    const int t2 = G / DD;
    const int c = t2 % NC;
    const int b = t2 / NC;

    const float Acoef = -expf(A_log[d * SS + s]);
    const float Dv = Dp[d];
    const int l0 = c * LC;

    const float* dtp = g_dt    + ((size_t)(b * LL + l0)) * DD + d;
    const float* xcp = g_xconv + ((size_t)(b * LL + l0)) * DD + d;
    const float* bcp = g_bc    + ((size_t)(b * LL + l0)) * 32;
    const float* zp  = g_xz    + ((size_t)(b * LL + l0)) * TWO_D + DD + d;
    const size_t obase = ((size_t)(b * LL + l0)) * DD + d;

    float h = g_hin[(((b * DD + d) * NC) + c) * SS + s];
    for (int i = 0; i < LC; i++) {
        float dtv = dtp[(size_t)i * DD];
        float xcv = xcp[(size_t)i * DD];
        float Bv  = bcp[i * 32 + s];
        float Cv  = bcp[i * 32 + 16 + s];

        float dA = expf(dtv * Acoef);
        h = fmaf(dA, h, dtv * Bv * xcv);

        float p = h * Cv;
        p += __shfl_xor_sync(0xffffffffu, p, 8);
        p += __shfl_xor_sync(0xffffffffu, p, 4);
        p += __shfl_xor_sync(0xffffffffu, p, 2);
        p += __shfl_xor_sync(0xffffffffu, p, 1);

        if (s == 0) {
            float y = fmaf(Dv, xcv, p);
            float zv = zp[(size_t)i * TWO_D];
            float gz = zv / (1.f + expf(-zv));
            float o = y * gz;
            uint16_t h16, l16;
            split1(o, h16, l16);
            g_yghi[obase + (size_t)i * DD] = h16;
            g_yglo[obase + (size_t)i * DD] = l16;
        }
    }
}

// ---------------- launch ----------------
extern "C" void kernel_launch(void* const* d_in, const int* in_sizes, int n_in,
                              void* d_out, int out_size)
{
    const float* x      = (const float*)d_in[0];
    const float* w_in   = (const float*)d_in[1];
    const float* conv_w = (const float*)d_in[2];
    const float* conv_b = (const float*)d_in[3];
    const float* w_x    = (const float*)d_in[4];
    const float* w_dt   = (const float*)d_in[5];
    const float* b_dt   = (const float*)d_in[6];
    const float* A_log  = (const float*)d_in[7];
    const float* D_par  = (const float*)d_in[8];
    const float* w_out  = (const float*)d_in[9];
    float* out = (float*)d_out;

    // 0. precompute bf16 operands (x split; weights transpose+split)
    convert_x_kernel<<<(MM * DD / 4 + 255) / 256, 256>>>(x);
    wtrans_in_kernel<<<dim3(TWO_D / 32, DD / 32), 256>>>(w_in);
    wtrans_dt_kernel<<<dim3(DD / 32, DD / 32), 256>>>(w_dt);
    wtrans_out_kernel<<<dim3(DD / 32, DD / 32), 256>>>(w_out);

    // 1. xz = x @ w_in                       (8192 x 1536, K=768)
    bf_gemm_in_kernel<<<dim3(TWO_D / 64, MM / 128), 256>>>();

    // 2. causal depthwise conv + SiLU (+ bf16 split of xconv)
    conv_silu_kernel<<<(MM * DD + 255) / 256, 256>>>(conv_w, conv_b);

    // 3. BC = xconv @ w_x                    (8192 x 32, K=768)
    bc_gemm_kernel<<<MM / 128, 256>>>(w_x);

    // 4. dt = softplus(xconv @ w_dt + b_dt)  (8192 x 768, K=768)  [profile slot]
    bf_gemm_dt_kernel<<<dim3(DD / 64, MM / 128), 256>>>(b_dt);

    // 5-7. chunked selective scan + gating   -> yghi/yglo (bf16 split)
    scan_phase1<<<(BB * DD * NC) / 16, 256>>>(A_log);
    scan_phase2<<<(BB * DD * SS) / 256, 256>>>();
    scan_phase3<<<(BB * DD * NC) / 16, 256>>>(A_log, D_par);

    // 8. out = yg @ w_out                    (8192 x 768, K=768)
    bf_gemm_out_kernel<<<dim3(DD / 64, MM / 128), 256>>>(out);
}